// round 13
// baseline (speedup 1.0000x reference)
#include <cuda_runtime.h>

#define DNUM 20
#define ONUM 19
#define MNUM 32
#define MM   1024
#define NAB  (ONUM * ONUM)                // 361
#define ROWOUT (ONUM * MNUM)              // 608

typedef unsigned long long u64;

// transposed tables: CT[k][j][i] = cos(2*pi*k/(32*i+j+2)), PT[j][i] = P[i][j]
__device__ __align__(16) float g_CT[ONUM * MM];
__device__ __align__(16) float g_PT[MM];

__device__ __forceinline__ u64 ffma2(u64 a, u64 b, u64 c) {
    u64 d;
    asm("fma.rn.f32x2 %0, %1, %2, %3;" : "=l"(d) : "l"(a), "l"(b), "l"(c));
    return d;
}
__device__ __forceinline__ u64 pk2(float lo, float hi) {
    u64 r;
    asm("mov.b64 %0, {%1, %2};" : "=l"(r) : "f"(lo), "f"(hi));
    return r;
}
__device__ __forceinline__ void upk2(u64 v, float& lo, float& hi) {
    asm("mov.b64 {%0, %1}, %2;" : "=f"(lo), "=f"(hi) : "l"(v));
}

__global__ void init_tabs(const float* __restrict__ P) {
    int t = blockIdx.x * blockDim.x + threadIdx.x;
    if (t < ONUM * MM) {
        int k = t / MM, r = t % MM;
        int j = r >> 5, i = r & 31;
        g_CT[t] = cosf(6.283185307179586f * (float)k / (float)(i * MNUM + j + 2));
    } else if (t < ONUM * MM + MM) {
        int e = t - ONUM * MM;                    // e = j*32 + i
        g_PT[e] = P[(e & 31) * MNUM + (e >> 5)];
    }
}

// Fused, c-eighth blocks: block = (a,b,cq), 128 threads, 8 blocks/SM.
#define FT 128                              // 4 warps
#define CQ 8
#define CRMAX 4                             // max c' rows (3 c-rows + halo)
#define H2F (CRMAX * DNUM * MNUM)           // 2560 floats
#define X2STR 33
#define X2F (CRMAX * DNUM * X2STR)          // 2640

__global__ __launch_bounds__(FT, 8) void fused(const float* __restrict__ h,
                                               const float* __restrict__ Mw,
                                               float* __restrict__ out) {
    __shared__ __align__(16) float sH2[H2F];   // A/B: H2[cl][d'][k]; C/D: WX[lc][j][d20]
    __shared__ __align__(16) float sX2[X2F];   // X2[cl][d'][j], stride 33
    __shared__ __align__(16) float sGab[MM];   // (P^T * Ca * Cb)[j][i]

    const int tid = threadIdx.x;
    const int blk = blockIdx.x;
    const int ab = blk >> 3, cq = blk & 7;
    const int a = ab / ONUM, b = ab % ONUM;
    // c splits: 3,3,3,2,2,2,2,2  (sum 19)
    const int crows = (cq < 3) ? 3 : 2;
    const int c0 = (cq < 3) ? 3 * cq : 9 + 2 * (cq - 3);
    const int cr = crows + 1;                  // c' rows incl. halo
    const int w = tid >> 5, lane = tid & 31;

    // phase A0: Gab = PT .* Ca .* Cb (two float4 per thread)
    {
#pragma unroll
        for (int q = 0; q < 2; ++q) {
            const int e = tid + q * FT;
            float4 p  = ((const float4*)g_PT)[e];
            float4 av = ((const float4*)(g_CT + a * MM))[e];
            float4 bv = ((const float4*)(g_CT + b * MM))[e];
            float4 o;
            o.x = p.x * av.x * bv.x;
            o.y = p.y * av.y * bv.y;
            o.z = p.z * av.z * bv.z;
            o.w = p.w * av.w * bv.w;
            ((float4*)sGab)[e] = o;
        }
    }

    // phase A: H2[cl][d'][k] = sum over {da,db} of h[a+da, b+db, c0+cl, d', k]
    // f4 base: (a*20+b)*3200 + c0*160; db:+3200, da:+64000 (in float4)
    {
        const float4* p00 = (const float4*)h + (a * DNUM + b) * 3200 + c0 * 160;
        float4* o4 = (float4*)sH2;
        const int tot = cr * 160;
        for (int e = tid; e < tot; e += FT) {
            float4 r0 = __ldg(p00 + e);
            float4 r1 = __ldg(p00 + e + 3200);
            float4 r2 = __ldg(p00 + e + 64000);
            float4 r3 = __ldg(p00 + e + 67200);
            float4 o;
            o.x = (r0.x + r1.x) + (r2.x + r3.x);
            o.y = (r0.y + r1.y) + (r2.y + r3.y);
            o.z = (r0.z + r1.z) + (r2.z + r3.z);
            o.w = (r0.w + r1.w) + (r2.w + r3.w);
            o4[e] = o;
        }
    }
    __syncthreads();

    // phase B: X2[cl][d'][j] = sum_k M[j,k] * H2[cl][d'][k]; lane = j, warp per pt
    {
        float Mr[MNUM];
        const float4* M4 = (const float4*)Mw + lane * 8;
#pragma unroll
        for (int v = 0; v < 8; ++v) {
            float4 m = __ldg(M4 + v);
            Mr[4*v+0] = m.x; Mr[4*v+1] = m.y; Mr[4*v+2] = m.z; Mr[4*v+3] = m.w;
        }
        const int npt = cr * DNUM;
        for (int pt = w; pt < npt; pt += FT / 32) {
            const float4* H4 = (const float4*)sH2 + pt * 8;
            float a0 = 0.f, a1 = 0.f, a2 = 0.f, a3 = 0.f;
#pragma unroll
            for (int v = 0; v < 8; ++v) {
                float4 hv = H4[v];                 // uniform LDS broadcast
                a0 = fmaf(Mr[4*v+0], hv.x, a0);
                a1 = fmaf(Mr[4*v+1], hv.y, a1);
                a2 = fmaf(Mr[4*v+2], hv.z, a2);
                a3 = fmaf(Mr[4*v+3], hv.w, a3);
            }
            sX2[pt * X2STR + lane] = (a0 + a1) + (a2 + a3);
        }
    }
    __syncthreads();

    // phase C: window over (c,d), transpose -> WX[lc][j][d(20, last=0)] over sH2
    {
        const int tot = crows * 160;
        for (int idx = tid; idx < tot; idx += FT) {
            const int lc = idx / 160, e = idx - lc * 160;
            const int f0 = e * 4;
            const int j0 = f0 / 20, d0 = f0 - (f0 / 20) * 20;  // 20%4==0
            const float* b0 = sX2 + (lc * DNUM + d0) * X2STR + j0;
            const float* b1 = b0 + DNUM * X2STR;
            float q[4];
#pragma unroll
            for (int t = 0; t < 4; ++t) {
                const int d = d0 + t;
                q[t] = (d < ONUM)
                     ? ((b0[t * X2STR] + b0[(t + 1) * X2STR])
                      + (b1[t * X2STR] + b1[(t + 1) * X2STR])) * 0.0625f
                     : 0.0f;
            }
            float4 v; v.x = q[0]; v.y = q[1]; v.z = q[2]; v.w = q[3];
            ((float4*)(sH2 + lc * 640))[e] = v;
        }
    }
    __syncthreads();

    // phase D: warp w = local row lc (< crows); lane = i; packed Chebyshev
    if (w < crows) {
        const int c = c0 + w;
        const float* Gl  = sGab + lane;
        const float* Cc  = g_CT + c * MM + lane;
        const float* C1  = g_CT + MM + lane;
        const ulonglong2* xs = (const ulonglong2*)(sH2 + w * 640);

        u64 acc[10];
#pragma unroll
        for (int k = 0; k < 10; ++k) acc[k] = 0ull;

#pragma unroll 2
        for (int j = 0; j < MNUM; ++j) {
            const int o = j * MNUM;
            const float tc = 2.0f * __ldg(C1 + o);
            const float u0 = Gl[o] * __ldg(Cc + o);
            const float csq = tc * tc;
            const u64 tc2  = pk2(csq - 2.0f, csq - 2.0f);
            const u64 ntc2 = pk2(2.0f - csq, 2.0f - csq);
            const float t1 = 0.5f * tc * u0;
            const float t2 = fmaf(tc, t1, -u0);
            const float t3 = fmaf(tc, t2, -t1);

            ulonglong2 xa = xs[j * 5 + 0];
            ulonglong2 xb = xs[j * 5 + 1];
            ulonglong2 xc = xs[j * 5 + 2];
            ulonglong2 xd = xs[j * 5 + 3];
            ulonglong2 xe = xs[j * 5 + 4];

            u64 s0 = pk2(u0, t1);
            u64 s1 = pk2(t2, t3);
            acc[0] = ffma2(xa.x, s0, acc[0]);
            acc[1] = ffma2(xa.y, s1, acc[1]);
            u64 s2 = ffma2(ntc2, s1, s0);
            acc[2] = ffma2(xb.x, s2, acc[2]);
            u64 s3 = ffma2(tc2, s2, s1);
            acc[3] = ffma2(xb.y, s3, acc[3]);
            s0 = ffma2(ntc2, s3, s2);
            acc[4] = ffma2(xc.x, s0, acc[4]);
            s1 = ffma2(tc2, s0, s3);
            acc[5] = ffma2(xc.y, s1, acc[5]);
            s2 = ffma2(ntc2, s1, s0);
            acc[6] = ffma2(xd.x, s2, acc[6]);
            s3 = ffma2(tc2, s2, s1);
            acc[7] = ffma2(xd.y, s3, acc[7]);
            s0 = ffma2(ntc2, s3, s2);
            acc[8] = ffma2(xe.x, s0, acc[8]);
            s1 = ffma2(tc2, s0, s3);
            acc[9] = ffma2(xe.y, s1, acc[9]);
        }

        float* op = out + (ab * ONUM + c) * ROWOUT + lane;
#pragma unroll
        for (int k = 0; k < 10; ++k) {
            float lo, hi;
            upk2(acc[k], lo, hi);
            const float s = (k & 2) ? -1.0f : 1.0f;
            op[(2 * k) * MNUM] = s * lo;
            if (2 * k + 1 < ONUM) op[(2 * k + 1) * MNUM] = s * hi;
        }
    }
}

extern "C" void kernel_launch(void* const* d_in, const int* in_sizes, int n_in,
                              void* d_out, int out_size) {
    const float* h  = (const float*)d_in[0];   // hypervol [20,20,20,20,32]
    const float* Mw = (const float*)d_in[1];   // M_w [32,32]
    const float* P  = (const float*)d_in[2];   // P  [32,32]
    float* out = (float*)d_out;                // [130321, 32]

    init_tabs<<<(ONUM * MM + MM + 511) / 512, 512>>>(P);
    fused<<<NAB * CQ, FT>>>(h, Mw, out);
}

// round 14
// speedup vs baseline: 1.6337x; 1.6337x over previous
#include <cuda_runtime.h>

#define DNUM 20
#define ONUM 19
#define MNUM 32
#define MM   1024
#define NAB  (ONUM * ONUM)                // 361
#define ROWOUT (ONUM * MNUM)              // 608

typedef unsigned long long u64;

// transposed tables: CT[k][j][i] = cos(2*pi*k/(32*i+j+2)), PT[j][i] = P[i][j]
__device__ __align__(16) float g_CT[ONUM * MM];
__device__ __align__(16) float g_PT[MM];

__device__ __forceinline__ u64 ffma2(u64 a, u64 b, u64 c) {
    u64 d;
    asm("fma.rn.f32x2 %0, %1, %2, %3;" : "=l"(d) : "l"(a), "l"(b), "l"(c));
    return d;
}
__device__ __forceinline__ u64 pk2(float lo, float hi) {
    u64 r;
    asm("mov.b64 %0, {%1, %2};" : "=l"(r) : "f"(lo), "f"(hi));
    return r;
}
__device__ __forceinline__ void upk2(u64 v, float& lo, float& hi) {
    asm("mov.b64 {%0, %1}, %2;" : "=f"(lo), "=f"(hi) : "l"(v));
}

__global__ void init_tabs(const float* __restrict__ P) {
    int t = blockIdx.x * blockDim.x + threadIdx.x;
    if (t < ONUM * MM) {
        int k = t / MM, r = t % MM;
        int j = r >> 5, i = r & 31;
        g_CT[t] = cosf(6.283185307179586f * (float)k / (float)(i * MNUM + j + 2));
    } else if (t < ONUM * MM + MM) {
        int e = t - ONUM * MM;                    // e = j*32 + i
        g_PT[e] = P[(e & 31) * MNUM + (e >> 5)];
    }
}

// Fused, c-fifth blocks: block = (a,b,cq), 192 threads, 5 blocks/SM.
#define FT 192                              // 6 warps
#define CQ 5
#define CRMAX 5                             // max c' rows (4 c-rows + halo)
#define H2F (CRMAX * DNUM * MNUM)           // 3200 floats
#define X2STR 33
#define X2F (CRMAX * DNUM * X2STR)          // 3300

__global__ __launch_bounds__(FT, 5) void fused(const float* __restrict__ h,
                                               const float* __restrict__ Mw,
                                               float* __restrict__ out) {
    __shared__ __align__(16) float sH2[H2F];   // A/B: H2[cl][d'][k]; C/D: WX[lc][j][d20]
    __shared__ __align__(16) float sX2[X2F];   // X2[cl][d'][j], stride 33
    __shared__ __align__(16) float sGab[MM];   // (P^T * Ca * Cb)[j][i]

    const int tid = threadIdx.x;
    const int blk = blockIdx.x;
    const int ab = blk / CQ, cq = blk - ab * CQ;
    const int a = ab / ONUM, b = ab % ONUM;
    // c splits: 4,4,4,4,3 (sum 19)
    const int crows = (cq < 4) ? 4 : 3;
    const int c0 = 4 * cq;
    const int cr = crows + 1;                  // c' rows incl. halo
    const int w = tid >> 5, lane = tid & 31;

    // phase A0: Gab = PT .* Ca .* Cb (256 float4 strided over 192 threads)
    for (int e = tid; e < MM / 4; e += FT) {
        float4 p  = ((const float4*)g_PT)[e];
        float4 av = ((const float4*)(g_CT + a * MM))[e];
        float4 bv = ((const float4*)(g_CT + b * MM))[e];
        float4 o;
        o.x = p.x * av.x * bv.x;
        o.y = p.y * av.y * bv.y;
        o.z = p.z * av.z * bv.z;
        o.w = p.w * av.w * bv.w;
        ((float4*)sGab)[e] = o;
    }

    // phase A: H2[cl][d'][k] = sum over {da,db} of h[a+da, b+db, c0+cl, d', k]
    // f4 base: (a*20+b)*3200 + c0*160; db:+3200, da:+64000 (in float4)
    {
        const float4* p00 = (const float4*)h + (a * DNUM + b) * 3200 + c0 * 160;
        float4* o4 = (float4*)sH2;
        const int tot = cr * 160;
        for (int e = tid; e < tot; e += FT) {
            float4 r0 = __ldg(p00 + e);
            float4 r1 = __ldg(p00 + e + 3200);
            float4 r2 = __ldg(p00 + e + 64000);
            float4 r3 = __ldg(p00 + e + 67200);
            float4 o;
            o.x = (r0.x + r1.x) + (r2.x + r3.x);
            o.y = (r0.y + r1.y) + (r2.y + r3.y);
            o.z = (r0.z + r1.z) + (r2.z + r3.z);
            o.w = (r0.w + r1.w) + (r2.w + r3.w);
            o4[e] = o;
        }
    }
    __syncthreads();

    // phase B: X2[cl][d'][j] = sum_k M[j,k] * H2[cl][d'][k]; lane = j, warp per pt
    {
        float Mr[MNUM];
        const float4* M4 = (const float4*)Mw + lane * 8;
#pragma unroll
        for (int v = 0; v < 8; ++v) {
            float4 m = __ldg(M4 + v);
            Mr[4*v+0] = m.x; Mr[4*v+1] = m.y; Mr[4*v+2] = m.z; Mr[4*v+3] = m.w;
        }
        const int npt = cr * DNUM;
        for (int pt = w; pt < npt; pt += FT / 32) {
            const float4* H4 = (const float4*)sH2 + pt * 8;
            float a0 = 0.f, a1 = 0.f, a2 = 0.f, a3 = 0.f;
#pragma unroll
            for (int v = 0; v < 8; ++v) {
                float4 hv = H4[v];                 // uniform LDS broadcast
                a0 = fmaf(Mr[4*v+0], hv.x, a0);
                a1 = fmaf(Mr[4*v+1], hv.y, a1);
                a2 = fmaf(Mr[4*v+2], hv.z, a2);
                a3 = fmaf(Mr[4*v+3], hv.w, a3);
            }
            sX2[pt * X2STR + lane] = (a0 + a1) + (a2 + a3);
        }
    }
    __syncthreads();

    // phase C: window over (c,d), transpose -> WX[lc][j][d(20, last=0)] over sH2
    {
        const int tot = crows * 160;
        for (int idx = tid; idx < tot; idx += FT) {
            const int lc = idx / 160, e = idx - lc * 160;
            const int f0 = e * 4;
            const int j0 = f0 / 20, d0 = f0 - (f0 / 20) * 20;  // 20%4==0
            const float* b0 = sX2 + (lc * DNUM + d0) * X2STR + j0;
            const float* b1 = b0 + DNUM * X2STR;
            float q[4];
#pragma unroll
            for (int t = 0; t < 4; ++t) {
                const int d = d0 + t;
                q[t] = (d < ONUM)
                     ? ((b0[t * X2STR] + b0[(t + 1) * X2STR])
                      + (b1[t * X2STR] + b1[(t + 1) * X2STR])) * 0.0625f
                     : 0.0f;
            }
            float4 v; v.x = q[0]; v.y = q[1]; v.z = q[2]; v.w = q[3];
            ((float4*)(sH2 + lc * 640))[e] = v;
        }
    }
    __syncthreads();

    // phase D: warp w = local row lc (< crows); lane = i; packed Chebyshev
    if (w < crows) {
        const int c = c0 + w;
        const float* Gl  = sGab + lane;
        const float* Cc  = g_CT + c * MM + lane;
        const float* C1  = g_CT + MM + lane;
        const ulonglong2* xs = (const ulonglong2*)(sH2 + w * 640);

        u64 acc[10];
#pragma unroll
        for (int k = 0; k < 10; ++k) acc[k] = 0ull;

#pragma unroll 2
        for (int j = 0; j < MNUM; ++j) {
            const int o = j * MNUM;
            const float tc = 2.0f * __ldg(C1 + o);
            const float u0 = Gl[o] * __ldg(Cc + o);
            const float csq = tc * tc;
            const u64 tc2  = pk2(csq - 2.0f, csq - 2.0f);
            const u64 ntc2 = pk2(2.0f - csq, 2.0f - csq);
            const float t1 = 0.5f * tc * u0;
            const float t2 = fmaf(tc, t1, -u0);
            const float t3 = fmaf(tc, t2, -t1);

            ulonglong2 xa = xs[j * 5 + 0];
            ulonglong2 xb = xs[j * 5 + 1];
            ulonglong2 xc = xs[j * 5 + 2];
            ulonglong2 xd = xs[j * 5 + 3];
            ulonglong2 xe = xs[j * 5 + 4];

            u64 s0 = pk2(u0, t1);
            u64 s1 = pk2(t2, t3);
            acc[0] = ffma2(xa.x, s0, acc[0]);
            acc[1] = ffma2(xa.y, s1, acc[1]);
            u64 s2 = ffma2(ntc2, s1, s0);
            acc[2] = ffma2(xb.x, s2, acc[2]);
            u64 s3 = ffma2(tc2, s2, s1);
            acc[3] = ffma2(xb.y, s3, acc[3]);
            s0 = ffma2(ntc2, s3, s2);
            acc[4] = ffma2(xc.x, s0, acc[4]);
            s1 = ffma2(tc2, s0, s3);
            acc[5] = ffma2(xc.y, s1, acc[5]);
            s2 = ffma2(ntc2, s1, s0);
            acc[6] = ffma2(xd.x, s2, acc[6]);
            s3 = ffma2(tc2, s2, s1);
            acc[7] = ffma2(xd.y, s3, acc[7]);
            s0 = ffma2(ntc2, s3, s2);
            acc[8] = ffma2(xe.x, s0, acc[8]);
            s1 = ffma2(tc2, s0, s3);
            acc[9] = ffma2(xe.y, s1, acc[9]);
        }

        float* op = out + (ab * ONUM + c) * ROWOUT + lane;
#pragma unroll
        for (int k = 0; k < 10; ++k) {
            float lo, hi;
            upk2(acc[k], lo, hi);
            const float s = (k & 2) ? -1.0f : 1.0f;
            op[(2 * k) * MNUM] = s * lo;
            if (2 * k + 1 < ONUM) op[(2 * k + 1) * MNUM] = s * hi;
        }
    }
}

extern "C" void kernel_launch(void* const* d_in, const int* in_sizes, int n_in,
                              void* d_out, int out_size) {
    const float* h  = (const float*)d_in[0];   // hypervol [20,20,20,20,32]
    const float* Mw = (const float*)d_in[1];   // M_w [32,32]
    const float* P  = (const float*)d_in[2];   // P  [32,32]
    float* out = (float*)d_out;                // [130321, 32]

    init_tabs<<<(ONUM * MM + MM + 511) / 512, 512>>>(P);
    fused<<<NAB * CQ, FT>>>(h, Mw, out);
}

// round 15
// speedup vs baseline: 1.9614x; 1.2006x over previous
#include <cuda_runtime.h>

#define DNUM 20
#define ONUM 19
#define MNUM 32
#define MM   1024
#define NAB  (ONUM * ONUM)                // 361
#define ROWOUT (ONUM * MNUM)              // 608

typedef unsigned long long u64;

// transposed tables: CT[k][j][i] = cos(2*pi*k/(32*i+j+2)), PT[j][i] = P[i][j]
__device__ __align__(16) float g_CT[ONUM * MM];
__device__ __align__(16) float g_PT[MM];
__constant__ __align__(16) float c_M[MM];          // M_w row-major [j][k]

__device__ __forceinline__ u64 ffma2(u64 a, u64 b, u64 c) {
    u64 d;
    asm("fma.rn.f32x2 %0, %1, %2, %3;" : "=l"(d) : "l"(a), "l"(b), "l"(c));
    return d;
}
__device__ __forceinline__ u64 pk2(float lo, float hi) {
    u64 r;
    asm("mov.b64 %0, {%1, %2};" : "=l"(r) : "f"(lo), "f"(hi));
    return r;
}
__device__ __forceinline__ void upk2(u64 v, float& lo, float& hi) {
    asm("mov.b64 {%0, %1}, %2;" : "=f"(lo), "=f"(hi) : "l"(v));
}

__global__ void init_tabs(const float* __restrict__ P) {
    int t = blockIdx.x * blockDim.x + threadIdx.x;
    if (t < ONUM * MM) {
        int k = t / MM, r = t % MM;
        int j = r >> 5, i = r & 31;
        g_CT[t] = cosf(6.283185307179586f * (float)k / (float)(i * MNUM + j + 2));
    } else if (t < ONUM * MM + MM) {
        int e = t - ONUM * MM;                    // e = j*32 + i
        g_PT[e] = P[(e & 31) * MNUM + (e >> 5)];
    }
}

// Fused, c-fifth blocks: block = (a,b,cq), 192 threads.
#define FT 192                              // 6 warps
#define CQ 5
#define CRMAX 5                             // max c' rows (4 c-rows + halo)
#define H2F (CRMAX * DNUM * MNUM)           // 3200 floats
#define X2STR 33
#define X2F (CRMAX * DNUM * X2STR)          // 3300

__global__ __launch_bounds__(FT, 5) void fused(const float* __restrict__ h,
                                               float* __restrict__ out) {
    __shared__ __align__(16) float sH2[H2F];   // A/B: swizzled H2; C/D: WX[lc][j][d20]
    __shared__ __align__(16) float sX2[X2F];   // X2[pt][j], stride 33
    __shared__ __align__(16) float sGab[MM];   // (P^T * Ca * Cb)[j][i]

    const int tid = threadIdx.x;
    const int blk = blockIdx.x;
    const int ab = blk / CQ, cq = blk - ab * CQ;
    const int a = ab / ONUM, b = ab % ONUM;
    // c splits: 4,4,4,4,3 (sum 19)
    const int crows = (cq < 4) ? 4 : 3;
    const int c0 = 4 * cq;
    const int cr = crows + 1;                  // c' rows incl. halo
    const int w = tid >> 5, lane = tid & 31;

    // phase A0: Gab = PT .* Ca .* Cb
    for (int e = tid; e < MM / 4; e += FT) {
        float4 p  = ((const float4*)g_PT)[e];
        float4 av = ((const float4*)(g_CT + a * MM))[e];
        float4 bv = ((const float4*)(g_CT + b * MM))[e];
        float4 o;
        o.x = p.x * av.x * bv.x;
        o.y = p.y * av.y * bv.y;
        o.z = p.z * av.z * bv.z;
        o.w = p.w * av.w * bv.w;
        ((float4*)sGab)[e] = o;
    }

    // phase A: H2[pt][k] = sum over {da,db} of h[a+da, b+db, c0+cl, d', k]
    // stored with f4-slot XOR swizzle: slot v' = v ^ (pt & 7)
    {
        const float4* p00 = (const float4*)h + (a * DNUM + b) * 3200 + c0 * 160;
        float4* o4 = (float4*)sH2;
        const int tot = cr * 160;
        for (int e = tid; e < tot; e += FT) {
            float4 r0 = __ldg(p00 + e);
            float4 r1 = __ldg(p00 + e + 3200);
            float4 r2 = __ldg(p00 + e + 64000);
            float4 r3 = __ldg(p00 + e + 67200);
            float4 o;
            o.x = (r0.x + r1.x) + (r2.x + r3.x);
            o.y = (r0.y + r1.y) + (r2.y + r3.y);
            o.z = (r0.z + r1.z) + (r2.z + r3.z);
            o.w = (r0.w + r1.w) + (r2.w + r3.w);
            const int sw = (e & ~7) | ((e ^ (e >> 3)) & 7);
            o4[sw] = o;
        }
    }
    __syncthreads();

    // phase B: thread pt computes x_j = sum_k M[j,k]*H2[pt,k] for all j.
    // H2 via lane-varying swizzled LDS.128 (conflict-free), M via constant port.
    {
        const int npt = cr * DNUM;                 // <= 100 < FT: one pass
        if (tid < npt) {
            const int pt = tid;
            const int sw = pt & 7;
            float H[MNUM];
#pragma unroll
            for (int v = 0; v < 8; ++v) {
                float4 hv = ((const float4*)sH2)[pt * 8 + (v ^ sw)];
                H[4*v+0] = hv.x; H[4*v+1] = hv.y;
                H[4*v+2] = hv.z; H[4*v+3] = hv.w;
            }
            float* xo = sX2 + pt * X2STR;
#pragma unroll
            for (int j = 0; j < MNUM; ++j) {
                float a0 = 0.f, a1 = 0.f, a2 = 0.f, a3 = 0.f;
#pragma unroll
                for (int v = 0; v < 8; ++v) {
                    a0 = fmaf(c_M[j*32+4*v+0], H[4*v+0], a0);
                    a1 = fmaf(c_M[j*32+4*v+1], H[4*v+1], a1);
                    a2 = fmaf(c_M[j*32+4*v+2], H[4*v+2], a2);
                    a3 = fmaf(c_M[j*32+4*v+3], H[4*v+3], a3);
                }
                xo[j] = (a0 + a1) + (a2 + a3);
            }
        }
    }
    __syncthreads();

    // phase C: window over (c,d), transpose -> WX[lc][j][d(20, last=0)] over sH2
    {
        const int tot = crows * 160;
        for (int idx = tid; idx < tot; idx += FT) {
            const int lc = idx / 160, e = idx - lc * 160;
            const int f0 = e * 4;
            const int j0 = f0 / 20, d0 = f0 - (f0 / 20) * 20;  // 20%4==0
            const float* b0 = sX2 + (lc * DNUM + d0) * X2STR + j0;
            const float* b1 = b0 + DNUM * X2STR;
            float q[4];
#pragma unroll
            for (int t = 0; t < 4; ++t) {
                const int d = d0 + t;
                q[t] = (d < ONUM)
                     ? ((b0[t * X2STR] + b0[(t + 1) * X2STR])
                      + (b1[t * X2STR] + b1[(t + 1) * X2STR])) * 0.0625f
                     : 0.0f;
            }
            float4 v; v.x = q[0]; v.y = q[1]; v.z = q[2]; v.w = q[3];
            ((float4*)(sH2 + lc * 640))[e] = v;
        }
    }
    __syncthreads();

    // phase D: warp w = local row lc (< crows); lane = i; packed Chebyshev
    if (w < crows) {
        const int c = c0 + w;
        const float* Gl  = sGab + lane;
        const float* Cc  = g_CT + c * MM + lane;
        const float* C1  = g_CT + MM + lane;
        const ulonglong2* xs = (const ulonglong2*)(sH2 + w * 640);

        u64 acc[10];
#pragma unroll
        for (int k = 0; k < 10; ++k) acc[k] = 0ull;

#pragma unroll 2
        for (int j = 0; j < MNUM; ++j) {
            const int o = j * MNUM;
            const float tc = 2.0f * __ldg(C1 + o);
            const float u0 = Gl[o] * __ldg(Cc + o);
            const float csq = tc * tc;
            const u64 tc2  = pk2(csq - 2.0f, csq - 2.0f);
            const u64 ntc2 = pk2(2.0f - csq, 2.0f - csq);
            const float t1 = 0.5f * tc * u0;
            const float t2 = fmaf(tc, t1, -u0);
            const float t3 = fmaf(tc, t2, -t1);

            ulonglong2 xa = xs[j * 5 + 0];
            ulonglong2 xb = xs[j * 5 + 1];
            ulonglong2 xc = xs[j * 5 + 2];
            ulonglong2 xd = xs[j * 5 + 3];
            ulonglong2 xe = xs[j * 5 + 4];

            u64 s0 = pk2(u0, t1);
            u64 s1 = pk2(t2, t3);
            acc[0] = ffma2(xa.x, s0, acc[0]);
            acc[1] = ffma2(xa.y, s1, acc[1]);
            u64 s2 = ffma2(ntc2, s1, s0);
            acc[2] = ffma2(xb.x, s2, acc[2]);
            u64 s3 = ffma2(tc2, s2, s1);
            acc[3] = ffma2(xb.y, s3, acc[3]);
            s0 = ffma2(ntc2, s3, s2);
            acc[4] = ffma2(xc.x, s0, acc[4]);
            s1 = ffma2(tc2, s0, s3);
            acc[5] = ffma2(xc.y, s1, acc[5]);
            s2 = ffma2(ntc2, s1, s0);
            acc[6] = ffma2(xd.x, s2, acc[6]);
            s3 = ffma2(tc2, s2, s1);
            acc[7] = ffma2(xd.y, s3, acc[7]);
            s0 = ffma2(ntc2, s3, s2);
            acc[8] = ffma2(xe.x, s0, acc[8]);
            s1 = ffma2(tc2, s0, s3);
            acc[9] = ffma2(xe.y, s1, acc[9]);
        }

        float* op = out + (ab * ONUM + c) * ROWOUT + lane;
#pragma unroll
        for (int k = 0; k < 10; ++k) {
            float lo, hi;
            upk2(acc[k], lo, hi);
            const float s = (k & 2) ? -1.0f : 1.0f;
            op[(2 * k) * MNUM] = s * lo;
            if (2 * k + 1 < ONUM) op[(2 * k + 1) * MNUM] = s * hi;
        }
    }
}

extern "C" void kernel_launch(void* const* d_in, const int* in_sizes, int n_in,
                              void* d_out, int out_size) {
    const float* h  = (const float*)d_in[0];   // hypervol [20,20,20,20,32]
    const float* Mw = (const float*)d_in[1];   // M_w [32,32]
    const float* P  = (const float*)d_in[2];   // P  [32,32]
    float* out = (float*)d_out;                // [130321, 32]

    cudaMemcpyToSymbolAsync(c_M, Mw, MM * sizeof(float), 0,
                            cudaMemcpyDeviceToDevice);
    init_tabs<<<(ONUM * MM + MM + 511) / 512, 512>>>(P);
    fused<<<NAB * CQ, FT>>>(h, out);
}

// round 16
// speedup vs baseline: 2.1446x; 1.0934x over previous
#include <cuda_runtime.h>

#define DNUM 20
#define ONUM 19
#define MNUM 32
#define MM   1024
#define NAB  (ONUM * ONUM)                // 361
#define ROWOUT (ONUM * MNUM)              // 608

typedef unsigned long long u64;

// transposed tables: CT[k][j][i] = cos(2*pi*k/(32*i+j+2)), PT[j][i] = P[i][j]
__device__ __align__(16) float g_CT[ONUM * MM];
__device__ __align__(16) float g_PT[MM];
__constant__ __align__(16) float c_M[MM];          // M_w row-major [j][k]

__device__ __forceinline__ u64 ffma2(u64 a, u64 b, u64 c) {
    u64 d;
    asm("fma.rn.f32x2 %0, %1, %2, %3;" : "=l"(d) : "l"(a), "l"(b), "l"(c));
    return d;
}
__device__ __forceinline__ u64 pk2(float lo, float hi) {
    u64 r;
    asm("mov.b64 %0, {%1, %2};" : "=l"(r) : "f"(lo), "f"(hi));
    return r;
}
__device__ __forceinline__ void upk2(u64 v, float& lo, float& hi) {
    asm("mov.b64 {%0, %1}, %2;" : "=f"(lo), "=f"(hi) : "l"(v));
}

__global__ void init_tabs(const float* __restrict__ P) {
    int t = blockIdx.x * blockDim.x + threadIdx.x;
    if (t < ONUM * MM) {
        int k = t / MM, r = t % MM;
        int j = r >> 5, i = r & 31;
        g_CT[t] = cosf(6.283185307179586f * (float)k / (float)(i * MNUM + j + 2));
    } else if (t < ONUM * MM + MM) {
        int e = t - ONUM * MM;                    // e = j*32 + i
        g_PT[e] = P[(e & 31) * MNUM + (e >> 5)];
    }
}

// Fused, c-fifth blocks: block = (a,b,cq), 128 threads, 7 blocks/SM.
#define FT 128                              // 4 warps
#define CQ 5
#define CRMAX 5                             // max c' rows (4 c-rows + halo)
#define H2F (CRMAX * DNUM * MNUM)           // 3200 floats
#define X2STR 33
#define X2F (CRMAX * DNUM * X2STR)          // 3300

__global__ __launch_bounds__(FT, 7) void fused(const float* __restrict__ h,
                                               float* __restrict__ out) {
    __shared__ __align__(16) float sH2[H2F];   // A/B: swizzled H2; C/D: WX[lc][j][d20]
    __shared__ __align__(16) float sX2[X2F];   // X2[pt][j], stride 33
    __shared__ __align__(16) float sGab[MM];   // (P^T * Ca * Cb)[j][i]

    const int tid = threadIdx.x;
    const int blk = blockIdx.x;
    const int ab = blk / CQ, cq = blk - ab * CQ;
    const int a = ab / ONUM, b = ab % ONUM;
    // c splits: 4,4,4,4,3 (sum 19)
    const int crows = (cq < 4) ? 4 : 3;
    const int c0 = 4 * cq;
    const int cr = crows + 1;                  // c' rows incl. halo
    const int w = tid >> 5, lane = tid & 31;

    // phase A0: Gab = PT .* Ca .* Cb
    for (int e = tid; e < MM / 4; e += FT) {
        float4 p  = ((const float4*)g_PT)[e];
        float4 av = ((const float4*)(g_CT + a * MM))[e];
        float4 bv = ((const float4*)(g_CT + b * MM))[e];
        float4 o;
        o.x = p.x * av.x * bv.x;
        o.y = p.y * av.y * bv.y;
        o.z = p.z * av.z * bv.z;
        o.w = p.w * av.w * bv.w;
        ((float4*)sGab)[e] = o;
    }

    // phase A: H2[pt][k] = sum over {da,db} of h[a+da, b+db, c0+cl, d', k]
    // stored with f4-slot XOR swizzle: slot v' = v ^ (pt & 7)
    {
        const float4* p00 = (const float4*)h + (a * DNUM + b) * 3200 + c0 * 160;
        float4* o4 = (float4*)sH2;
        const int tot = cr * 160;
        for (int e = tid; e < tot; e += FT) {
            float4 r0 = __ldg(p00 + e);
            float4 r1 = __ldg(p00 + e + 3200);
            float4 r2 = __ldg(p00 + e + 64000);
            float4 r3 = __ldg(p00 + e + 67200);
            float4 o;
            o.x = (r0.x + r1.x) + (r2.x + r3.x);
            o.y = (r0.y + r1.y) + (r2.y + r3.y);
            o.z = (r0.z + r1.z) + (r2.z + r3.z);
            o.w = (r0.w + r1.w) + (r2.w + r3.w);
            const int sw = (e & ~7) | ((e ^ (e >> 3)) & 7);
            o4[sw] = o;
        }
    }
    __syncthreads();

    // phase B: thread pt computes x_j = sum_k M[j,k]*H2[pt,k] for all j.
    // H2 via lane-varying swizzled LDS.128; M via 64-bit constant loads; FFMA2.
    {
        const int npt = cr * DNUM;                 // <= 100 < FT: one pass
        if (tid < npt) {
            const int pt = tid;
            const int sw = pt & 7;
            u64 Hp[16];
#pragma unroll
            for (int v = 0; v < 8; ++v) {
                float4 hv = ((const float4*)sH2)[pt * 8 + (v ^ sw)];
                Hp[2*v]   = pk2(hv.x, hv.y);
                Hp[2*v+1] = pk2(hv.z, hv.w);
            }
            const u64* M2 = (const u64*)c_M;       // [j][kpair]
            float* xo = sX2 + pt * X2STR;
#pragma unroll
            for (int j = 0; j < MNUM; ++j) {
                u64 a0 = 0ull, a1 = 0ull, a2 = 0ull, a3 = 0ull;
#pragma unroll
                for (int v = 0; v < 4; ++v) {
                    a0 = ffma2(M2[j*16 + 4*v + 0], Hp[4*v + 0], a0);
                    a1 = ffma2(M2[j*16 + 4*v + 1], Hp[4*v + 1], a1);
                    a2 = ffma2(M2[j*16 + 4*v + 2], Hp[4*v + 2], a2);
                    a3 = ffma2(M2[j*16 + 4*v + 3], Hp[4*v + 3], a3);
                }
                float l0, h0, l1, h1, l2, h2, l3, h3;
                upk2(a0, l0, h0); upk2(a1, l1, h1);
                upk2(a2, l2, h2); upk2(a3, l3, h3);
                xo[j] = ((l0 + h0) + (l1 + h1)) + ((l2 + h2) + (l3 + h3));
            }
        }
    }
    __syncthreads();

    // phase C: window over (c,d), transpose -> WX[lc][j][d(20, last=0)] over sH2
    {
        const int tot = crows * 160;
        for (int idx = tid; idx < tot; idx += FT) {
            const int lc = idx / 160, e = idx - lc * 160;
            const int f0 = e * 4;
            const int j0 = f0 / 20, d0 = f0 - (f0 / 20) * 20;  // 20%4==0
            const float* b0 = sX2 + (lc * DNUM + d0) * X2STR + j0;
            const float* b1 = b0 + DNUM * X2STR;
            float q[4];
#pragma unroll
            for (int t = 0; t < 4; ++t) {
                const int d = d0 + t;
                q[t] = (d < ONUM)
                     ? ((b0[t * X2STR] + b0[(t + 1) * X2STR])
                      + (b1[t * X2STR] + b1[(t + 1) * X2STR])) * 0.0625f
                     : 0.0f;
            }
            float4 v; v.x = q[0]; v.y = q[1]; v.z = q[2]; v.w = q[3];
            ((float4*)(sH2 + lc * 640))[e] = v;
        }
    }
    __syncthreads();

    // phase D: warp w = local row lc (< crows); lane = i; packed Chebyshev
    if (w < crows) {
        const int c = c0 + w;
        const float* Gl  = sGab + lane;
        const float* Cc  = g_CT + c * MM + lane;
        const float* C1  = g_CT + MM + lane;
        const ulonglong2* xs = (const ulonglong2*)(sH2 + w * 640);

        u64 acc[10];
#pragma unroll
        for (int k = 0; k < 10; ++k) acc[k] = 0ull;

#pragma unroll 2
        for (int j = 0; j < MNUM; ++j) {
            const int o = j * MNUM;
            const float tc = 2.0f * __ldg(C1 + o);
            const float u0 = Gl[o] * __ldg(Cc + o);
            const float csq = tc * tc;
            const u64 tc2  = pk2(csq - 2.0f, csq - 2.0f);
            const u64 ntc2 = pk2(2.0f - csq, 2.0f - csq);
            const float t1 = 0.5f * tc * u0;
            const float t2 = fmaf(tc, t1, -u0);
            const float t3 = fmaf(tc, t2, -t1);

            ulonglong2 xa = xs[j * 5 + 0];
            ulonglong2 xb = xs[j * 5 + 1];
            ulonglong2 xc = xs[j * 5 + 2];
            ulonglong2 xd = xs[j * 5 + 3];
            ulonglong2 xe = xs[j * 5 + 4];

            u64 s0 = pk2(u0, t1);
            u64 s1 = pk2(t2, t3);
            acc[0] = ffma2(xa.x, s0, acc[0]);
            acc[1] = ffma2(xa.y, s1, acc[1]);
            u64 s2 = ffma2(ntc2, s1, s0);
            acc[2] = ffma2(xb.x, s2, acc[2]);
            u64 s3 = ffma2(tc2, s2, s1);
            acc[3] = ffma2(xb.y, s3, acc[3]);
            s0 = ffma2(ntc2, s3, s2);
            acc[4] = ffma2(xc.x, s0, acc[4]);
            s1 = ffma2(tc2, s0, s3);
            acc[5] = ffma2(xc.y, s1, acc[5]);
            s2 = ffma2(ntc2, s1, s0);
            acc[6] = ffma2(xd.x, s2, acc[6]);
            s3 = ffma2(tc2, s2, s1);
            acc[7] = ffma2(xd.y, s3, acc[7]);
            s0 = ffma2(ntc2, s3, s2);
            acc[8] = ffma2(xe.x, s0, acc[8]);
            s1 = ffma2(tc2, s0, s3);
            acc[9] = ffma2(xe.y, s1, acc[9]);
        }

        float* op = out + (ab * ONUM + c) * ROWOUT + lane;
#pragma unroll
        for (int k = 0; k < 10; ++k) {
            float lo, hi;
            upk2(acc[k], lo, hi);
            const float s = (k & 2) ? -1.0f : 1.0f;
            op[(2 * k) * MNUM] = s * lo;
            if (2 * k + 1 < ONUM) op[(2 * k + 1) * MNUM] = s * hi;
        }
    }
}

extern "C" void kernel_launch(void* const* d_in, const int* in_sizes, int n_in,
                              void* d_out, int out_size) {
    const float* h  = (const float*)d_in[0];   // hypervol [20,20,20,20,32]
    const float* Mw = (const float*)d_in[1];   // M_w [32,32]
    const float* P  = (const float*)d_in[2];   // P  [32,32]
    float* out = (float*)d_out;                // [130321, 32]

    cudaMemcpyToSymbolAsync(c_M, Mw, MM * sizeof(float), 0,
                            cudaMemcpyDeviceToDevice);
    init_tabs<<<(ONUM * MM + MM + 511) / 512, 512>>>(P);
    fused<<<NAB * CQ, FT>>>(h, out);
}